// round 17
// baseline (speedup 1.0000x reference)
#include <cuda_runtime.h>
#include <cstdint>

#define SBINS   8192       // smem histogram bins (atomic-conflict optimum)
#define NBINS   2048       // merged/output bins (4-fold of SBINS)
#define BDIM    4          // batch (fixed for this problem)
#define RMAX    7
#define NC      36         // chunks per batch image -> hist grid = 4*36 = 144
#define THREADS 1024
#define VMAXW   32768      // max V/32 supported (V <= 1M)

// Scratch (static device globals: allocation-free rule; zero-initialized)
__device__ unsigned g_bits[RMAX * BDIM * VMAXW];      // bit-packed masks
__device__ int    g_merged[RMAX * BDIM * NBINS];      // RED-merged histograms
__device__ int    g_cnt[BDIM * NC * RMAX];
__device__ double g_pnum[RMAX * BDIM];
__device__ int    g_pden[RMAX * BDIM];
__device__ int    g_ticket = 0;                       // finalize ticket (self-reset)

__device__ __forceinline__ int binf(float x) {
    int k = __float2int_rz(x * (float)SBINS);
    return min(max(k, 0), SBINS - 1);
}

// Kernel 0: bit-pack masks. Warp reads 32 consecutive int32 mask elems
// (coalesced 128B), ballot -> one output word. Pure streaming, no atomics.
__global__ void __launch_bounds__(THREADS)
pack_kernel(const int* __restrict__ mask, int words_total)
{
    const int lane = threadIdx.x & 31;
    const int gw   = blockIdx.x * (THREADS / 32) + (threadIdx.x >> 5);
    const int wpg  = gridDim.x * (THREADS / 32);
    for (int w = gw; w < words_total; w += wpg) {
        int m = __ldcs(mask + (size_t)w * 32 + lane);
        unsigned bits = __ballot_sync(0xffffffffu, m != 0);
        if (lane == 0) g_bits[w] = bits;
    }
}

// Kernel 1: RR signed histograms (cntP - cntG) at 8192 smem bins, one chunk of
// one batch image. Masks come from g_bits (32x smaller). Flush folds 4->1 and
// RED-merges into g_merged directly.
template <int RR>
__global__ void __launch_bounds__(THREADS, 1)
hist_kernel(const float* __restrict__ pred,
            const float* __restrict__ tgt,
            int V, int CH)
{
    extern __shared__ int sh[];               // RR * SBINS signed counters
    __shared__ int scnt[RR];

    const int t = threadIdx.x;
    #pragma unroll
    for (int j = t; j < RR * SBINS; j += THREADS) sh[j] = 0;
    if (t < RR) scnt[t] = 0;

    const int cid = blockIdx.x;
    const int b   = cid & (BDIM - 1);
    const int c   = cid >> 2;
    const int VW  = V >> 5;                   // words per (r,b) row

    const float* pp = pred + (size_t)b * V;
    const float* gp = tgt  + (size_t)b * V;
    const unsigned* bp = g_bits + (size_t)b * VW;   // ROI r at + r*BDIM*VW

    const int start = c * CH;                 // CH multiple of 32 -> aligned
    const int end   = min(V, start + CH);
    const unsigned sh5 = (unsigned)((t * 4) & 31);  // nibble shift, fixed per thread

    int cnt[RR];
    #pragma unroll
    for (int r = 0; r < RR; r++) cnt[r] = 0;
    __syncthreads();

    for (int off = start + t * 4; off < end; off += THREADS * 4) {
        float4 pv = __ldcs(reinterpret_cast<const float4*>(pp + off));
        float4 gv = __ldcs(reinterpret_cast<const float4*>(gp + off));
        const int wi = off >> 5;
        unsigned nib[RR];
        #pragma unroll
        for (int r = 0; r < RR; r++)
            nib[r] = (bp[(size_t)(r * BDIM) * VW + wi] >> sh5) & 15u;

        int p0 = binf(pv.x), p1 = binf(pv.y), p2 = binf(pv.z), p3 = binf(pv.w);
        int q0 = binf(gv.x), q1 = binf(gv.y), q2 = binf(gv.z), q3 = binf(gv.w);

        #pragma unroll
        for (int r = 0; r < RR; r++) {
            unsigned n = nib[r];
            if (n) {
                int* h = sh + r * SBINS;
                if (n & 1u) { atomicAdd(h + p0, 1); atomicAdd(h + q0, -1); }
                if (n & 2u) { atomicAdd(h + p1, 1); atomicAdd(h + q1, -1); }
                if (n & 4u) { atomicAdd(h + p2, 1); atomicAdd(h + q2, -1); }
                if (n & 8u) { atomicAdd(h + p3, 1); atomicAdd(h + q3, -1); }
                cnt[r] += __popc(n);
            }
        }
    }
    __syncthreads();

    // fold-flush: merged bin j = sum of smem bins [4j, 4j+4); RED straight
    // into g_merged. floor(x*8192)>>2 == floor(x*2048) -> identical results.
    #pragma unroll
    for (int j = t; j < RR * NBINS; j += THREADS) {
        int rr  = j >> 11;                    // NBINS == 2048
        int bin = j & (NBINS - 1);
        const int* hb = sh + rr * SBINS + bin * 4;
        int d = hb[0] + hb[1] + hb[2] + hb[3];
        if (d) atomicAdd(&g_merged[(size_t)(rr * BDIM + b) * NBINS + bin], d);
    }

    // per-ROI masked counts
    #pragma unroll
    for (int r = 0; r < RR; r++) {
        int v = cnt[r];
        #pragma unroll
        for (int d = 16; d; d >>= 1) v += __shfl_down_sync(0xffffffffu, v, d);
        if ((t & 31) == 0 && v) atomicAdd(&scnt[r], v);
    }
    __syncthreads();
    if (t < RR) g_cnt[cid * RR + t] = scnt[t];
}

// Slim tail: 24 CTAs x 1024 thr. Thread t owns bins (2t, 2t+1): one int2 load,
// block prefix-scan, sum |cum|, re-zero own slots (graph-replay determinism).
// Last-arriving CTA finalizes d_out.
__global__ void __launch_bounds__(THREADS, 1)
tail_kernel(float* __restrict__ outp, int R, int RB)
{
    __shared__ int wsum[33];
    __shared__ long long wacc[32];
    __shared__ int sden;

    const int rb = blockIdx.x;
    const int b  = rb & 3;
    const int r  = rb >> 2;
    const int t  = threadIdx.x, lane = t & 31, w = t >> 5;

    int2* slot = reinterpret_cast<int2*>(g_merged + (size_t)rb * NBINS + 2 * t);
    int2 v = *slot;
    *slot = make_int2(0, 0);                  // self-reset for next replay
    int local = v.x + v.y;

    int x = local;                            // warp inclusive scan
    #pragma unroll
    for (int d = 1; d < 32; d <<= 1) {
        int y = __shfl_up_sync(0xffffffffu, x, d);
        if (lane >= d) x += y;
    }
    if (lane == 31) wsum[w + 1] = x;
    if (t == 0) { sden = 0; wsum[0] = 0; }
    __syncthreads();
    if (t == 0)
        for (int i = 1; i < 32; i++) wsum[i + 1] += wsum[i];
    __syncthreads();

    int cum = wsum[w] + x - local;            // exclusive prefix for this thread
    int acc = 0;
    cum += v.x; acc += cum < 0 ? -cum : cum;
    cum += v.y; acc += cum < 0 ? -cum : cum;

    long long a = acc;
    #pragma unroll
    for (int d = 16; d; d >>= 1) a += __shfl_down_sync(0xffffffffu, a, d);
    if (lane == 0) wacc[w] = a;

    if (t < NC) atomicAdd(&sden, g_cnt[(t * BDIM + b) * R + r]);
    __syncthreads();

    if (t == 0) {
        long long s = 0;
        #pragma unroll
        for (int i = 0; i < 32; i++) s += wacc[i];
        g_pnum[rb] = (double)s * (52.0 / (double)NBINS);
        g_pden[rb] = sden;
        __threadfence();

        int old = atomicAdd(&g_ticket, 1);
        if (old == RB - 1) {                  // last CTA: finalize
            g_ticket = 0;                     // self-reset for graph replays
            __threadfence();
            volatile double* vn = g_pnum;
            volatile int*    vd = g_pden;
            double ls = 0.0;
            int cv = 0;
            for (int bb = 0; bb < BDIM; bb++) {
                double num = 0.0; long long dn = 0;
                for (int rr = 0; rr < RB / BDIM; rr++) {
                    num += vn[rr * BDIM + bb];
                    dn  += vd[rr * BDIM + bb];
                }
                if (dn > 0) {
                    ls += num / (double)(dn < 1 ? 1 : dn);
                    cv++;
                }
            }
            outp[0] = (float)(ls / (double)(cv > 0 ? cv : 1));
        }
    }
}

template <int RR>
static void launch_hist(const float* p, const float* g, int V, int CH)
{
    int smem = RR * SBINS * 4;                // 192 KB for RR=6 -> occ 1
    cudaFuncSetAttribute(hist_kernel<RR>, cudaFuncAttributeMaxDynamicSharedMemorySize, smem);
    hist_kernel<RR><<<BDIM * NC, THREADS, smem>>>(p, g, V, CH);
}

extern "C" void kernel_launch(void* const* d_in, const int* in_sizes, int n_in,
                              void* d_out, int out_size)
{
    const float* pred = (const float*)d_in[0];
    const float* tgt  = (const float*)d_in[1];
    const int*   mask = (const int*)d_in[2];

    int BV = in_sizes[0];                     // B*V = 4194304
    int V  = BV / BDIM;                       // 1048576 (multiple of 32)
    int R  = in_sizes[2] / BV;                // 6
    int RB = R * BDIM;                        // 24
    int CH = ((V + NC - 1) / NC + 31) & ~31;  // chunk, multiple of 32

    int words_total = RB * (V >> 5);          // 786432
    pack_kernel<<<296, THREADS>>>(mask, words_total);

    switch (R) {
        case 1: launch_hist<1>(pred, tgt, V, CH); break;
        case 2: launch_hist<2>(pred, tgt, V, CH); break;
        case 3: launch_hist<3>(pred, tgt, V, CH); break;
        case 4: launch_hist<4>(pred, tgt, V, CH); break;
        case 5: launch_hist<5>(pred, tgt, V, CH); break;
        case 7: launch_hist<7>(pred, tgt, V, CH); break;
        default:
        case 6: launch_hist<6>(pred, tgt, V, CH); break;
    }
    tail_kernel<<<RB, THREADS>>>((float*)d_out, R, RB);
}